// round 1
// baseline (speedup 1.0000x reference)
#include <cuda_runtime.h>
#include <cuda_bf16.h>
#include <math.h>

// Problem constants
#define BATCH 2
#define SEQ 2048
#define DM 1024
#define HEADS 16
#define DH 64
#define DFF 4096
#define TOK (BATCH*SEQ)          // 4096 tokens

// ---------------- scratch (static device globals; no allocs allowed) ----------
__device__ float g_h  [TOK*DM];     // ln output / reused
__device__ float g_q  [TOK*DM];
__device__ float g_k  [TOK*DM];
__device__ float g_v  [TOK*DM];
__device__ float g_kt [BATCH*HEADS*DH*SEQ]; // [b][h][d][s]
__device__ float g_ctx[TOK*DM];
__device__ float g_x2 [TOK*DM];     // after O-proj + residual
__device__ float g_ff [TOK*DFF];    // fc1 output

// ---------------- LayerNorm: one block per row of 1024 ------------------------
__global__ __launch_bounds__(256)
void ln_kernel(const float* __restrict__ x, const float* __restrict__ g,
               const float* __restrict__ b, float* __restrict__ out)
{
    int row = blockIdx.x;
    int tid = threadIdx.x;
    const float4* xr = reinterpret_cast<const float4*>(x + (size_t)row*DM);
    float4 v = xr[tid];
    float s  = v.x + v.y + v.z + v.w;
    float s2 = v.x*v.x + v.y*v.y + v.z*v.z + v.w*v.w;

    __shared__ float red[64];
    // warp reduce
    for (int o = 16; o; o >>= 1) {
        s  += __shfl_xor_sync(0xffffffffu, s,  o);
        s2 += __shfl_xor_sync(0xffffffffu, s2, o);
    }
    int warp = tid >> 5, lane = tid & 31;
    if (lane == 0) { red[warp] = s; red[32+warp] = s2; }
    __syncthreads();
    if (warp == 0) {
        float a = (lane < 8) ? red[lane] : 0.f;
        float c = (lane < 8) ? red[32+lane] : 0.f;
        for (int o = 4; o; o >>= 1) {
            a += __shfl_xor_sync(0xffffffffu, a, o);
            c += __shfl_xor_sync(0xffffffffu, c, o);
        }
        if (lane == 0) { red[0] = a; red[1] = c; }
    }
    __syncthreads();
    float mu  = red[0] * (1.0f/DM);
    float var = red[1] * (1.0f/DM) - mu*mu;
    float rstd = rsqrtf(var + 1e-5f);

    float4 gv = reinterpret_cast<const float4*>(g)[tid];
    float4 bv = reinterpret_cast<const float4*>(b)[tid];
    float4 o4;
    o4.x = (v.x - mu)*rstd*gv.x + bv.x;
    o4.y = (v.y - mu)*rstd*gv.y + bv.y;
    o4.z = (v.z - mu)*rstd*gv.z + bv.z;
    o4.w = (v.w - mu)*rstd*gv.w + bv.w;
    reinterpret_cast<float4*>(out + (size_t)row*DM)[tid] = o4;
}

// ---------------- SGEMM 128x128x8, 256 threads, 8x8 per thread ----------------
// C[M,N] = A[M,K] @ B[K,N]  (+bias) (gelu) (+R)
template<bool BIAS, bool GELU, bool RES>
__global__ __launch_bounds__(256)
void sgemm(const float* __restrict__ A, const float* __restrict__ B,
           const float* __restrict__ bias, const float* __restrict__ R,
           float* __restrict__ C, int M, int N, int K)
{
    const int BM = 128, BN = 128, BK = 8;
    __shared__ float As[BK][BM];
    __shared__ float Bs[BK][BN];

    int tid = threadIdx.x;
    int cRow = blockIdx.y, cCol = blockIdx.x;

    A += (size_t)cRow*BM*K;
    B += (size_t)cCol*BN;
    size_t coff = (size_t)cRow*BM*N + (size_t)cCol*BN;
    C += coff;
    if (RES) R += coff;

    int innerRowA = tid >> 1;          // 0..127
    int innerColA = tid & 1;           // float4 idx within 8
    int innerRowB = tid >> 5;          // 0..7
    int innerColB = tid & 31;          // float4 idx within 128

    int threadRow = tid >> 4;          // 0..15
    int threadCol = tid & 15;          // 0..15

    float acc[8][8];
    #pragma unroll
    for (int i = 0; i < 8; i++)
        #pragma unroll
        for (int j = 0; j < 8; j++) acc[i][j] = 0.f;

    float regM[8], regN[8];

    for (int kb = 0; kb < K; kb += BK) {
        float4 a4 = reinterpret_cast<const float4*>(&A[(size_t)innerRowA*K + innerColA*4])[0];
        As[innerColA*4+0][innerRowA] = a4.x;
        As[innerColA*4+1][innerRowA] = a4.y;
        As[innerColA*4+2][innerRowA] = a4.z;
        As[innerColA*4+3][innerRowA] = a4.w;
        float4 b4 = reinterpret_cast<const float4*>(&B[(size_t)innerRowB*N + innerColB*4])[0];
        reinterpret_cast<float4*>(&Bs[innerRowB][innerColB*4])[0] = b4;
        __syncthreads();
        A += BK;
        B += (size_t)BK*N;
        #pragma unroll
        for (int k = 0; k < BK; k++) {
            #pragma unroll
            for (int i = 0; i < 8; i++) regM[i] = As[k][threadRow*8 + i];
            #pragma unroll
            for (int j = 0; j < 8; j++) regN[j] = Bs[k][threadCol*8 + j];
            #pragma unroll
            for (int i = 0; i < 8; i++)
                #pragma unroll
                for (int j = 0; j < 8; j++)
                    acc[i][j] += regM[i] * regN[j];
        }
        __syncthreads();
    }

    #pragma unroll
    for (int i = 0; i < 8; i++) {
        int row = threadRow*8 + i;
        #pragma unroll
        for (int j4 = 0; j4 < 8; j4 += 4) {
            int col = threadCol*8 + j4;
            float o[4];
            #pragma unroll
            for (int t = 0; t < 4; t++) {
                float val = acc[i][j4+t];
                if (BIAS) val += bias[cCol*BN + col + t];
                if (GELU) val = 0.5f*val*(1.0f + erff(val*0.70710678118654752f));
                o[t] = val;
            }
            if (RES) {
                float4 r4 = reinterpret_cast<const float4*>(&R[(size_t)row*N + col])[0];
                o[0] += r4.x; o[1] += r4.y; o[2] += r4.z; o[3] += r4.w;
            }
            float4 o4 = make_float4(o[0], o[1], o[2], o[3]);
            reinterpret_cast<float4*>(&C[(size_t)row*N + col])[0] = o4;
        }
    }
}

// ---------------- K transpose: [B,S,H*DH] -> [B,H,DH,S] ------------------------
__global__ __launch_bounds__(256)
void transpose_k(const float* __restrict__ k, float* __restrict__ kt)
{
    int idx = blockIdx.x*256 + threadIdx.x;           // total BATCH*HEADS*DH*SEQ
    int s = idx & (SEQ-1);
    int r = idx >> 11;
    int d = r & (DH-1);
    int r2 = r >> 6;
    int h = r2 & (HEADS-1);
    int b = r2 >> 4;
    kt[idx] = k[((size_t)(b*SEQ + s))*DM + h*DH + d];
}

// ---------------- Attention: one block per (b,h,q-row) ------------------------
__global__ __launch_bounds__(256)
void attention_kernel(const float* __restrict__ q, const float* __restrict__ kt,
                      const float* __restrict__ v, const unsigned char* __restrict__ mask,
                      float* __restrict__ ctx)
{
    int qi = blockIdx.x, h = blockIdx.y, b = blockIdx.z;
    int tid = threadIdx.x;

    __shared__ float sc[SEQ];
    __shared__ float qrow[DH];
    __shared__ float red[8];
    __shared__ float part[4][DH];
    __shared__ float stat[2];

    if (tid < DH)
        qrow[tid] = q[((size_t)(b*SEQ + qi))*DM + h*DH + tid] * 0.125f; // /sqrt(64)
    __syncthreads();

    const float* ktp = kt + ((size_t)(b*HEADS + h))*DH*SEQ;

    float acc[8];
    #pragma unroll
    for (int jj = 0; jj < 8; jj++) acc[jj] = 0.f;
    for (int d = 0; d < DH; d++) {
        float qd = qrow[d];
        const float* kr = ktp + (size_t)d*SEQ;
        #pragma unroll
        for (int jj = 0; jj < 8; jj++)
            acc[jj] += qd * kr[tid + jj*256];
    }

    const unsigned char* mrow = mask + ((size_t)(b*SEQ + qi))*SEQ;
    float lmax = -1e30f;
    #pragma unroll
    for (int jj = 0; jj < 8; jj++) {
        int j = tid + jj*256;
        float sv = mrow[j] ? -1e9f : acc[jj];
        sc[j] = sv;
        lmax = fmaxf(lmax, sv);
    }
    // block max
    for (int o = 16; o; o >>= 1) lmax = fmaxf(lmax, __shfl_xor_sync(0xffffffffu, lmax, o));
    int warp = tid >> 5, lane = tid & 31;
    if (lane == 0) red[warp] = lmax;
    __syncthreads();
    if (tid == 0) {
        float m = red[0];
        #pragma unroll
        for (int w = 1; w < 8; w++) m = fmaxf(m, red[w]);
        stat[0] = m;
    }
    __syncthreads();
    float m = stat[0];

    float lsum = 0.f;
    #pragma unroll
    for (int jj = 0; jj < 8; jj++) {
        int j = tid + jj*256;
        float e = __expf(sc[j] - m);
        sc[j] = e;
        lsum += e;
    }
    for (int o = 16; o; o >>= 1) lsum += __shfl_xor_sync(0xffffffffu, lsum, o);
    if (lane == 0) red[warp] = lsum;
    __syncthreads();
    if (tid == 0) {
        float s = 0.f;
        #pragma unroll
        for (int w = 0; w < 8; w++) s += red[w];
        stat[1] = 1.0f / s;
    }
    __syncthreads();
    float inv = stat[1];

    // ctx: thread (chunk, d) accumulates over 512 keys
    int d = tid & 63;
    int chunk = tid >> 6;
    const float* vp = v + (size_t)b*SEQ*DM + h*DH + d;
    float a = 0.f;
    int j0 = chunk*512;
    for (int j = j0; j < j0 + 512; j++)
        a += sc[j] * vp[(size_t)j*DM];
    part[chunk][d] = a;
    __syncthreads();
    if (tid < DH) {
        float o = (part[0][tid] + part[1][tid] + part[2][tid] + part[3][tid]) * inv;
        ctx[((size_t)(b*SEQ + qi))*DM + h*DH + tid] = o;
    }
}

// ---------------- launch ------------------------------------------------------
extern "C" void kernel_launch(void* const* d_in, const int* in_sizes, int n_in,
                              void* d_out, int out_size)
{
    const float* x        = (const float*)d_in[0];
    const unsigned char* pad = (const unsigned char*)d_in[1];
    const float* W_Q   = (const float*)d_in[2];
    const float* W_K   = (const float*)d_in[3];
    const float* W_V   = (const float*)d_in[4];
    const float* W_O   = (const float*)d_in[5];
    const float* fc1_w = (const float*)d_in[6];
    const float* fc1_b = (const float*)d_in[7];
    const float* fc2_w = (const float*)d_in[8];
    const float* fc2_b = (const float*)d_in[9];
    const float* ln1_g = (const float*)d_in[10];
    const float* ln1_b = (const float*)d_in[11];
    const float* ln2_g = (const float*)d_in[12];
    const float* ln2_b = (const float*)d_in[13];
    float* out = (float*)d_out;

    float *h, *q, *k, *v, *kt, *ctx, *x2, *ff;
    cudaGetSymbolAddress((void**)&h,   g_h);
    cudaGetSymbolAddress((void**)&q,   g_q);
    cudaGetSymbolAddress((void**)&k,   g_k);
    cudaGetSymbolAddress((void**)&v,   g_v);
    cudaGetSymbolAddress((void**)&kt,  g_kt);
    cudaGetSymbolAddress((void**)&ctx, g_ctx);
    cudaGetSymbolAddress((void**)&x2,  g_x2);
    cudaGetSymbolAddress((void**)&ff,  g_ff);

    // 1) LN1
    ln_kernel<<<TOK, 256>>>(x, ln1_g, ln1_b, h);

    // 2) QKV projections
    dim3 gQ(DM/128, TOK/128);
    sgemm<false,false,false><<<gQ, 256>>>(h, W_Q, nullptr, nullptr, q, TOK, DM, DM);
    sgemm<false,false,false><<<gQ, 256>>>(h, W_K, nullptr, nullptr, k, TOK, DM, DM);
    sgemm<false,false,false><<<gQ, 256>>>(h, W_V, nullptr, nullptr, v, TOK, DM, DM);

    // 3) K transpose to [B,H,DH,S]
    transpose_k<<<(BATCH*HEADS*DH*SEQ)/256, 256>>>(k, kt);

    // 4) attention
    dim3 gA(SEQ, HEADS, BATCH);
    attention_kernel<<<gA, 256>>>(q, kt, v, pad, ctx);

    // 5) O-proj + residual(x)
    sgemm<false,false,true><<<gQ, 256>>>(ctx, W_O, nullptr, x, x2, TOK, DM, DM);

    // 6) LN2
    ln_kernel<<<TOK, 256>>>(x2, ln2_g, ln2_b, h);

    // 7) FC1 + bias + gelu
    dim3 gF1(DFF/128, TOK/128);
    sgemm<true,true,false><<<gF1, 256>>>(h, fc1_w, fc1_b, nullptr, ff, TOK, DFF, DM);

    // 8) FC2 + bias + residual(x2) -> out
    sgemm<true,false,true><<<gQ, 256>>>(ff, fc2_w, fc2_b, x2, out, TOK, DM, DFF);
}

// round 2
// speedup vs baseline: 6.3504x; 6.3504x over previous
#include <cuda_runtime.h>
#include <cuda_fp16.h>
#include <math.h>
#include <stdint.h>

#define BATCH 2
#define SEQ 2048
#define DM 1024
#define HEADS 16
#define DH 64
#define DFF 4096
#define TOK (BATCH*SEQ)

// ---------------- scratch (device globals; no allocs allowed) -----------------
__device__ __half g_hh [TOK*DM];
__device__ __half g_qh [TOK*DM];
__device__ __half g_kh [TOK*DM];
__device__ __half g_vh [TOK*DM];
__device__ __half g_kt [BATCH*HEADS*DH*SEQ];          // [b][h][d][s]
__device__ float  g_sc [BATCH*HEADS*SEQ*SEQ];         // 512MB fp32 scores
__device__ __half g_pr [BATCH*HEADS*SEQ*SEQ];         // 256MB half probs
__device__ __half g_ctx[TOK*DM];
__device__ float  g_x2 [TOK*DM];
__device__ __half g_ff [TOK*DFF];
__device__ __half g_wq[DM*DM], g_wk[DM*DM], g_wv[DM*DM], g_wo[DM*DM];
__device__ __half g_w1[DM*DFF], g_w2[DFF*DM];

// ---------------- PTX helpers --------------------------------------------------
__device__ __forceinline__ uint32_t smem_u32(const void* p) {
    return (uint32_t)__cvta_generic_to_shared(p);
}
#define CP_ASYNC16(dst, src) asm volatile("cp.async.cg.shared.global [%0], [%1], 16;\n" :: "r"(dst), "l"(src))
#define CP_COMMIT() asm volatile("cp.async.commit_group;\n")
#define CP_WAIT(N)  asm volatile("cp.async.wait_group %0;\n" :: "n"(N))

#define LDSM4(r0,r1,r2,r3,addr) \
    asm volatile("ldmatrix.sync.aligned.m8n8.x4.shared.b16 {%0,%1,%2,%3},[%4];" \
        : "=r"(r0),"=r"(r1),"=r"(r2),"=r"(r3) : "r"(addr))
#define LDSM4T(r0,r1,r2,r3,addr) \
    asm volatile("ldmatrix.sync.aligned.m8n8.x4.trans.shared.b16 {%0,%1,%2,%3},[%4];" \
        : "=r"(r0),"=r"(r1),"=r"(r2),"=r"(r3) : "r"(addr))

#define MMA16816(c0,c1,c2,c3,a0,a1,a2,a3,b0,b1) \
    asm volatile("mma.sync.aligned.m16n8k16.row.col.f32.f16.f16.f32 " \
        "{%0,%1,%2,%3},{%4,%5,%6,%7},{%8,%9},{%0,%1,%2,%3};" \
        : "+f"(c0),"+f"(c1),"+f"(c2),"+f"(c3) \
        : "r"(a0),"r"(a1),"r"(a2),"r"(a3),"r"(b0),"r"(b1))

__device__ __forceinline__ float gelu_f(float v) {
    return 0.5f * v * (1.0f + erff(v * 0.70710678118654752f));
}

// ---------------- half GEMM (mma.sync), templated epilogue ---------------------
// C[M,N](+z-batch) = A(half)[M,K] @ B(half)[K,N]; epilogue: *oscale, +bias, gelu,
// +R(fp32), mask->-1e9; out fp32 or half.
template<int BM,int BN,int WM,int WN,bool BIAS,bool GELU,bool RES,bool MASK,bool OUTH>
__global__ void __launch_bounds__(256,2)
hgemm(const __half* __restrict__ A, int lda, long aSB, long aSH,
      const __half* __restrict__ B, int ldb, long bSB, long bSH,
      const float* __restrict__ bias,
      const float* __restrict__ R, int ldr,
      const unsigned char* __restrict__ mask,
      void* __restrict__ Cv, int ldc, long cSB, long cSH,
      int M, int N, int K, float oscale)
{
    const int BK = 32;
    const int WNUM_M = BM / WM;              // warps along M
    const int MT = WM / 16, NT = WN / 8, NP = NT / 2;
    __shared__ __half As[2][BM][BK + 8];     // row 80B = 5*16B -> conflict-free ldmatrix
    __shared__ __half Bs[2][BK][BN + 8];     // row (BN+8)*2B = odd*16B -> conflict-free

    int z  = blockIdx.z;
    int zb = z >> 4, zh = z & 15;
    A += zb * aSB + zh * aSH;
    B += zb * bSB + zh * bSH;
    if (MASK) mask += (size_t)zb * (size_t)M * N;

    int rowBase = blockIdx.y * BM;
    int colBase = blockIdx.x * BN;

    int tid  = threadIdx.x;
    int warp = tid >> 5, lane = tid & 31;
    int wm = warp % WNUM_M, wn = warp / WNUM_M;

    const int CA = BM * BK / 8 / 256;        // cp.async16 per thread for A tile
    const int CB = BK * BN / 8 / 256;        // ... for B tile

    float acc[MT][NT][4];
    #pragma unroll
    for (int mt = 0; mt < MT; mt++)
        #pragma unroll
        for (int nt = 0; nt < NT; nt++)
            #pragma unroll
            for (int i = 0; i < 4; i++) acc[mt][nt][i] = 0.f;

    auto stage = [&](int buf, int kb) {
        #pragma unroll
        for (int j = 0; j < CA; j++) {
            int idx = j * 256 + tid;
            int r  = idx >> 2;               // BK/8 == 4
            int c8 = (idx & 3) * 8;
            CP_ASYNC16(smem_u32(&As[buf][r][c8]),
                       A + (size_t)(rowBase + r) * lda + kb + c8);
        }
        #pragma unroll
        for (int j = 0; j < CB; j++) {
            int idx = j * 256 + tid;
            int kr = idx / (BN / 8);
            int c8 = (idx % (BN / 8)) * 8;
            CP_ASYNC16(smem_u32(&Bs[buf][kr][c8]),
                       B + (size_t)(kb + kr) * ldb + colBase + c8);
        }
    };

    int nk = K / BK;
    stage(0, 0); CP_COMMIT();

    for (int i = 0; i < nk; i++) {
        if (i + 1 < nk) { stage((i + 1) & 1, (i + 1) * BK); CP_COMMIT(); CP_WAIT(1); }
        else            { CP_WAIT(0); }
        __syncthreads();
        int buf = i & 1;
        #pragma unroll
        for (int ks = 0; ks < 2; ks++) {
            uint32_t a[MT][4];
            #pragma unroll
            for (int mt = 0; mt < MT; mt++) {
                uint32_t ad = smem_u32(&As[buf][wm * WM + mt * 16 + (lane & 15)]
                                               [ks * 16 + (lane >> 4) * 8]);
                LDSM4(a[mt][0], a[mt][1], a[mt][2], a[mt][3], ad);
            }
            uint32_t b[NP][4];
            #pragma unroll
            for (int np = 0; np < NP; np++) {
                uint32_t ad = smem_u32(&Bs[buf][ks * 16 + (lane & 15)]
                                               [wn * WN + np * 16 + (lane >> 4) * 8]);
                LDSM4T(b[np][0], b[np][1], b[np][2], b[np][3], ad);
            }
            #pragma unroll
            for (int mt = 0; mt < MT; mt++)
                #pragma unroll
                for (int nt = 0; nt < NT; nt++) {
                    uint32_t b0 = b[nt >> 1][(nt & 1) * 2];
                    uint32_t b1 = b[nt >> 1][(nt & 1) * 2 + 1];
                    MMA16816(acc[mt][nt][0], acc[mt][nt][1], acc[mt][nt][2], acc[mt][nt][3],
                             a[mt][0], a[mt][1], a[mt][2], a[mt][3], b0, b1);
                }
        }
        __syncthreads();
    }

    // ---------------- epilogue ----------------
    __half* Ch = (__half*)Cv + zb * cSB + zh * cSH;
    float*  Cf = (float*) Cv + zb * cSB + zh * cSH;

    #pragma unroll
    for (int mt = 0; mt < MT; mt++) {
        int r0 = rowBase + wm * WM + mt * 16 + (lane >> 2);
        #pragma unroll
        for (int nt = 0; nt < NT; nt++) {
            int c = colBase + wn * WN + nt * 8 + (lane & 3) * 2;
            #pragma unroll
            for (int hh = 0; hh < 2; hh++) {
                int r = r0 + hh * 8;
                float v0 = acc[mt][nt][hh * 2 + 0] * oscale;
                float v1 = acc[mt][nt][hh * 2 + 1] * oscale;
                if (BIAS) { v0 += bias[c]; v1 += bias[c + 1]; }
                if (GELU) { v0 = gelu_f(v0); v1 = gelu_f(v1); }
                if (RES)  {
                    float2 rr = *(const float2*)(R + (size_t)r * ldr + c);
                    v0 += rr.x; v1 += rr.y;
                }
                if (MASK) {
                    const unsigned char* mp = mask + (size_t)r * N + c;
                    if (mp[0]) v0 = -1e9f;
                    if (mp[1]) v1 = -1e9f;
                }
                if (OUTH) *(__half2*)(Ch + (size_t)r * ldc + c) = __floats2half2_rn(v0, v1);
                else      *(float2*) (Cf + (size_t)r * ldc + c) = make_float2(v0, v1);
            }
        }
    }
}

// ---------------- fp32 -> half convert ----------------------------------------
__global__ __launch_bounds__(256)
void cvt_kernel(const float* __restrict__ s, __half* __restrict__ d, int n)
{
    int i = (blockIdx.x * 256 + threadIdx.x) * 4;
    if (i < n) {
        float4 v = *(const float4*)(s + i);
        *(__half2*)(d + i)     = __floats2half2_rn(v.x, v.y);
        *(__half2*)(d + i + 2) = __floats2half2_rn(v.z, v.w);
    }
}

// ---------------- LayerNorm -> half --------------------------------------------
__global__ __launch_bounds__(256)
void ln_half_kernel(const float* __restrict__ x, const float* __restrict__ g,
                    const float* __restrict__ b, __half* __restrict__ out)
{
    int row = blockIdx.x;
    int tid = threadIdx.x;
    float4 v = reinterpret_cast<const float4*>(x + (size_t)row * DM)[tid];
    float s  = v.x + v.y + v.z + v.w;
    float s2 = v.x * v.x + v.y * v.y + v.z * v.z + v.w * v.w;

    __shared__ float red[64];
    for (int o = 16; o; o >>= 1) {
        s  += __shfl_xor_sync(0xffffffffu, s,  o);
        s2 += __shfl_xor_sync(0xffffffffu, s2, o);
    }
    int warp = tid >> 5, lane = tid & 31;
    if (lane == 0) { red[warp] = s; red[32 + warp] = s2; }
    __syncthreads();
    if (warp == 0) {
        float a = (lane < 8) ? red[lane] : 0.f;
        float c = (lane < 8) ? red[32 + lane] : 0.f;
        for (int o = 4; o; o >>= 1) {
            a += __shfl_xor_sync(0xffffffffu, a, o);
            c += __shfl_xor_sync(0xffffffffu, c, o);
        }
        if (lane == 0) { red[0] = a; red[1] = c; }
    }
    __syncthreads();
    float mu   = red[0] * (1.0f / DM);
    float var  = red[1] * (1.0f / DM) - mu * mu;
    float rstd = rsqrtf(var + 1e-5f);

    float4 gv = reinterpret_cast<const float4*>(g)[tid];
    float4 bv = reinterpret_cast<const float4*>(b)[tid];
    float o0 = (v.x - mu) * rstd * gv.x + bv.x;
    float o1 = (v.y - mu) * rstd * gv.y + bv.y;
    float o2 = (v.z - mu) * rstd * gv.z + bv.z;
    float o3 = (v.w - mu) * rstd * gv.w + bv.w;
    __half2* op = reinterpret_cast<__half2*>(out + (size_t)row * DM);
    op[tid * 2]     = __floats2half2_rn(o0, o1);
    op[tid * 2 + 1] = __floats2half2_rn(o2, o3);
}

// ---------------- K transpose (half): [B,S,H*DH] -> [B,H,DH,S] -----------------
__global__ __launch_bounds__(256)
void transpose_k_half(const __half* __restrict__ k, __half* __restrict__ kt)
{
    int idx = blockIdx.x * 256 + threadIdx.x;
    int s = idx & (SEQ - 1);
    int r = idx >> 11;
    int d = r & (DH - 1);
    int h = (r >> 6) & (HEADS - 1);
    int b = r >> 10;
    kt[idx] = k[((size_t)(b * SEQ + s)) * DM + h * DH + d];
}

// ---------------- row softmax: fp32 scores -> half probs -----------------------
__global__ __launch_bounds__(256)
void softmax_kernel(const float* __restrict__ sc, __half* __restrict__ pr)
{
    size_t base = (size_t)blockIdx.x * SEQ;
    int tid = threadIdx.x, lane = tid & 31, warp = tid >> 5;
    __shared__ float red[8];
    __shared__ float sm, si;

    float v[8];
    float m = -1e30f;
    #pragma unroll
    for (int j = 0; j < 8; j++) { v[j] = sc[base + tid + j * 256]; m = fmaxf(m, v[j]); }
    for (int o = 16; o; o >>= 1) m = fmaxf(m, __shfl_xor_sync(0xffffffffu, m, o));
    if (lane == 0) red[warp] = m;
    __syncthreads();
    if (tid == 0) {
        float t = red[0];
        #pragma unroll
        for (int w = 1; w < 8; w++) t = fmaxf(t, red[w]);
        sm = t;
    }
    __syncthreads();
    m = sm;

    float s = 0.f;
    #pragma unroll
    for (int j = 0; j < 8; j++) { v[j] = __expf(v[j] - m); s += v[j]; }
    for (int o = 16; o; o >>= 1) s += __shfl_xor_sync(0xffffffffu, s, o);
    if (lane == 0) red[warp] = s;
    __syncthreads();
    if (tid == 0) {
        float t = 0.f;
        #pragma unroll
        for (int w = 0; w < 8; w++) t += red[w];
        si = 1.0f / t;
    }
    __syncthreads();
    float inv = si;
    #pragma unroll
    for (int j = 0; j < 8; j++)
        pr[base + tid + j * 256] = __float2half_rn(v[j] * inv);
}

// ---------------- launch --------------------------------------------------------
extern "C" void kernel_launch(void* const* d_in, const int* in_sizes, int n_in,
                              void* d_out, int out_size)
{
    const float* x     = (const float*)d_in[0];
    const unsigned char* pad = (const unsigned char*)d_in[1];
    const float* W_Q   = (const float*)d_in[2];
    const float* W_K   = (const float*)d_in[3];
    const float* W_V   = (const float*)d_in[4];
    const float* W_O   = (const float*)d_in[5];
    const float* fc1_w = (const float*)d_in[6];
    const float* fc1_b = (const float*)d_in[7];
    const float* fc2_w = (const float*)d_in[8];
    const float* fc2_b = (const float*)d_in[9];
    const float* ln1_g = (const float*)d_in[10];
    const float* ln1_b = (const float*)d_in[11];
    const float* ln2_g = (const float*)d_in[12];
    const float* ln2_b = (const float*)d_in[13];
    float* out = (float*)d_out;

    __half *hh, *qh, *kh, *vh, *kt, *pr, *ctxh, *ff, *wq, *wk, *wv, *wo, *w1, *w2;
    float *sc, *x2;
    cudaGetSymbolAddress((void**)&hh,   g_hh);
    cudaGetSymbolAddress((void**)&qh,   g_qh);
    cudaGetSymbolAddress((void**)&kh,   g_kh);
    cudaGetSymbolAddress((void**)&vh,   g_vh);
    cudaGetSymbolAddress((void**)&kt,   g_kt);
    cudaGetSymbolAddress((void**)&sc,   g_sc);
    cudaGetSymbolAddress((void**)&pr,   g_pr);
    cudaGetSymbolAddress((void**)&ctxh, g_ctx);
    cudaGetSymbolAddress((void**)&x2,   g_x2);
    cudaGetSymbolAddress((void**)&ff,   g_ff);
    cudaGetSymbolAddress((void**)&wq,   g_wq);
    cudaGetSymbolAddress((void**)&wk,   g_wk);
    cudaGetSymbolAddress((void**)&wv,   g_wv);
    cudaGetSymbolAddress((void**)&wo,   g_wo);
    cudaGetSymbolAddress((void**)&w1,   g_w1);
    cudaGetSymbolAddress((void**)&w2,   g_w2);

    // 0) weights -> half
    cvt_kernel<<<DM*DM/1024, 256>>>(W_Q, wq, DM*DM);
    cvt_kernel<<<DM*DM/1024, 256>>>(W_K, wk, DM*DM);
    cvt_kernel<<<DM*DM/1024, 256>>>(W_V, wv, DM*DM);
    cvt_kernel<<<DM*DM/1024, 256>>>(W_O, wo, DM*DM);
    cvt_kernel<<<DM*DFF/1024, 256>>>(fc1_w, w1, DM*DFF);
    cvt_kernel<<<DFF*DM/1024, 256>>>(fc2_w, w2, DFF*DM);

    // 1) LN1 -> half
    ln_half_kernel<<<TOK, 256>>>(x, ln1_g, ln1_b, hh);

    // 2) QKV projections (q pre-scaled by 1/sqrt(dk))
    dim3 gP(DM/128, TOK/128, 1);
    hgemm<128,128,64,32,false,false,false,false,true><<<gP,256>>>(
        hh, DM, 0,0, wq, DM, 0,0, nullptr, nullptr,0, nullptr,
        qh, DM, 0,0, TOK, DM, DM, 0.125f);
    hgemm<128,128,64,32,false,false,false,false,true><<<gP,256>>>(
        hh, DM, 0,0, wk, DM, 0,0, nullptr, nullptr,0, nullptr,
        kh, DM, 0,0, TOK, DM, DM, 1.0f);
    hgemm<128,128,64,32,false,false,false,false,true><<<gP,256>>>(
        hh, DM, 0,0, wv, DM, 0,0, nullptr, nullptr,0, nullptr,
        vh, DM, 0,0, TOK, DM, DM, 1.0f);

    // 3) K transpose
    transpose_k_half<<<BATCH*HEADS*DH*SEQ/256, 256>>>(kh, kt);

    // 4) scores = q @ k^T (masked), fp32  — batched over z = b*16 + h
    dim3 gS(SEQ/128, SEQ/128, BATCH*HEADS);
    hgemm<128,128,64,32,false,false,false,true,false><<<gS,256>>>(
        qh, DM, (long)SEQ*DM, (long)DH,
        kt, SEQ, (long)HEADS*DH*SEQ, (long)DH*SEQ,
        nullptr, nullptr, 0, pad,
        sc, SEQ, (long)HEADS*SEQ*SEQ, (long)SEQ*SEQ,
        SEQ, SEQ, DH, 1.0f);

    // 5) softmax rows -> half probs
    softmax_kernel<<<BATCH*HEADS*SEQ, 256>>>(sc, pr);

    // 6) ctx = probs @ V  (half out, head-interleaved layout [tok][1024])
    dim3 gV(DH/64, SEQ/128, BATCH*HEADS);
    hgemm<128,64,64,16,false,false,false,false,true><<<gV,256>>>(
        pr, SEQ, (long)HEADS*SEQ*SEQ, (long)SEQ*SEQ,
        vh, DM, (long)SEQ*DM, (long)DH,
        nullptr, nullptr, 0, nullptr,
        ctxh, DM, (long)SEQ*DM, (long)DH,
        SEQ, DH, SEQ, 1.0f);

    // 7) O-proj + residual(x) -> x2 fp32
    hgemm<128,128,64,32,false,false,true,false,false><<<gP,256>>>(
        ctxh, DM, 0,0, wo, DM, 0,0, nullptr, x, DM, nullptr,
        x2, DM, 0,0, TOK, DM, DM, 1.0f);

    // 8) LN2 -> half
    ln_half_kernel<<<TOK, 256>>>(x2, ln2_g, ln2_b, hh);

    // 9) FC1 + bias + gelu -> half
    dim3 gF(DFF/128, TOK/128, 1);
    hgemm<128,128,64,32,true,true,false,false,true><<<gF,256>>>(
        hh, DM, 0,0, w1, DFF, 0,0, fc1_b, nullptr,0, nullptr,
        ff, DFF, 0,0, TOK, DFF, DM, 1.0f);

    // 10) FC2 + bias + residual(x2) -> out fp32
    hgemm<128,128,64,32,true,false,true,false,false><<<gP,256>>>(
        ff, DFF, 0,0, w2, DM, 0,0, fc2_b, x2, DM, nullptr,
        out, DM, 0,0, TOK, DM, DFF, 1.0f);
}

// round 4
// speedup vs baseline: 9.7907x; 1.5418x over previous
#include <cuda_runtime.h>
#include <cuda_fp16.h>
#include <math.h>
#include <stdint.h>

#define BATCH 2
#define SEQ 2048
#define DM 1024
#define HEADS 16
#define DH 64
#define DFF 4096
#define TOK (BATCH*SEQ)

// ---------------- scratch (device globals; no allocs allowed) -----------------
__device__ __half g_hh [TOK*DM];
__device__ __half g_qh [TOK*DM];
__device__ __half g_kh [TOK*DM];
__device__ __half g_vh [TOK*DM];
__device__ __half g_ctx[TOK*DM];
__device__ float  g_x2 [TOK*DM];
__device__ __half g_ff [TOK*DFF];
__device__ __half g_wq[DM*DM], g_wk[DM*DM], g_wv[DM*DM], g_wo[DM*DM];
__device__ __half g_w1[DM*DFF], g_w2[DFF*DM];

// ---------------- PTX helpers --------------------------------------------------
__device__ __forceinline__ uint32_t smem_u32(const void* p) {
    return (uint32_t)__cvta_generic_to_shared(p);
}
#define CP_ASYNC16(dst, src) asm volatile("cp.async.cg.shared.global [%0], [%1], 16;\n" :: "r"(dst), "l"(src))
#define CP_COMMIT() asm volatile("cp.async.commit_group;\n")
#define CP_WAIT(N)  asm volatile("cp.async.wait_group %0;\n" :: "n"(N))

#define LDSM4(r0,r1,r2,r3,addr) \
    asm volatile("ldmatrix.sync.aligned.m8n8.x4.shared.b16 {%0,%1,%2,%3},[%4];" \
        : "=r"(r0),"=r"(r1),"=r"(r2),"=r"(r3) : "r"(addr))
#define LDSM4T(r0,r1,r2,r3,addr) \
    asm volatile("ldmatrix.sync.aligned.m8n8.x4.trans.shared.b16 {%0,%1,%2,%3},[%4];" \
        : "=r"(r0),"=r"(r1),"=r"(r2),"=r"(r3) : "r"(addr))

#define MMA16816(c0,c1,c2,c3,a0,a1,a2,a3,b0,b1) \
    asm volatile("mma.sync.aligned.m16n8k16.row.col.f32.f16.f16.f32 " \
        "{%0,%1,%2,%3},{%4,%5,%6,%7},{%8,%9},{%0,%1,%2,%3};" \
        : "+f"(c0),"+f"(c1),"+f"(c2),"+f"(c3) \
        : "r"(a0),"r"(a1),"r"(a2),"r"(a3),"r"(b0),"r"(b1))

__device__ __forceinline__ float gelu_f(float v) {
    return 0.5f * v * (1.0f + erff(v * 0.70710678118654752f));
}
__device__ __forceinline__ uint32_t h2u(float a, float b) {
    __half2 h = __floats2half2_rn(a, b);
    return *(uint32_t*)&h;
}

// ---------------- half GEMM (mma.sync), templated epilogue ---------------------
template<int BM,int BN,int WM,int WN,bool BIAS,bool GELU,bool RES,bool OUTH>
__global__ void __launch_bounds__(256,2)
hgemm(const __half* __restrict__ A, int lda,
      const __half* __restrict__ B, int ldb,
      const float* __restrict__ bias,
      const float* __restrict__ R, int ldr,
      void* __restrict__ Cv, int ldc,
      int M, int N, int K, float oscale)
{
    const int BK = 32;
    const int WNUM_M = BM / WM;
    const int MT = WM / 16, NT = WN / 8, NP = NT / 2;
    __shared__ __half As[2][BM][BK + 8];
    __shared__ __half Bs[2][BK][BN + 8];

    int rowBase = blockIdx.y * BM;
    int colBase = blockIdx.x * BN;

    int tid  = threadIdx.x;
    int warp = tid >> 5, lane = tid & 31;
    int wm = warp % WNUM_M, wn = warp / WNUM_M;

    const int CA = BM * BK / 8 / 256;
    const int CB = BK * BN / 8 / 256;

    float acc[MT][NT][4];
    #pragma unroll
    for (int mt = 0; mt < MT; mt++)
        #pragma unroll
        for (int nt = 0; nt < NT; nt++)
            #pragma unroll
            for (int i = 0; i < 4; i++) acc[mt][nt][i] = 0.f;

    auto stage = [&](int buf, int kb) {
        #pragma unroll
        for (int j = 0; j < CA; j++) {
            int idx = j * 256 + tid;
            int r  = idx >> 2;
            int c8 = (idx & 3) * 8;
            CP_ASYNC16(smem_u32(&As[buf][r][c8]),
                       A + (size_t)(rowBase + r) * lda + kb + c8);
        }
        #pragma unroll
        for (int j = 0; j < CB; j++) {
            int idx = j * 256 + tid;
            int kr = idx / (BN / 8);
            int c8 = (idx % (BN / 8)) * 8;
            CP_ASYNC16(smem_u32(&Bs[buf][kr][c8]),
                       B + (size_t)(kb + kr) * ldb + colBase + c8);
        }
    };

    int nk = K / BK;
    stage(0, 0); CP_COMMIT();

    for (int i = 0; i < nk; i++) {
        if (i + 1 < nk) { stage((i + 1) & 1, (i + 1) * BK); CP_COMMIT(); CP_WAIT(1); }
        else            { CP_WAIT(0); }
        __syncthreads();
        int buf = i & 1;
        #pragma unroll
        for (int ks = 0; ks < 2; ks++) {
            uint32_t a[MT][4];
            #pragma unroll
            for (int mt = 0; mt < MT; mt++) {
                uint32_t ad = smem_u32(&As[buf][wm * WM + mt * 16 + (lane & 15)]
                                               [ks * 16 + (lane >> 4) * 8]);
                LDSM4(a[mt][0], a[mt][1], a[mt][2], a[mt][3], ad);
            }
            uint32_t b[NP][4];
            #pragma unroll
            for (int np = 0; np < NP; np++) {
                uint32_t ad = smem_u32(&Bs[buf][ks * 16 + (lane & 15)]
                                               [wn * WN + np * 16 + (lane >> 4) * 8]);
                LDSM4T(b[np][0], b[np][1], b[np][2], b[np][3], ad);
            }
            #pragma unroll
            for (int mt = 0; mt < MT; mt++)
                #pragma unroll
                for (int nt = 0; nt < NT; nt++) {
                    uint32_t b0 = b[nt >> 1][(nt & 1) * 2];
                    uint32_t b1 = b[nt >> 1][(nt & 1) * 2 + 1];
                    MMA16816(acc[mt][nt][0], acc[mt][nt][1], acc[mt][nt][2], acc[mt][nt][3],
                             a[mt][0], a[mt][1], a[mt][2], a[mt][3], b0, b1);
                }
        }
        __syncthreads();
    }

    __half* Ch = (__half*)Cv;
    float*  Cf = (float*) Cv;

    #pragma unroll
    for (int mt = 0; mt < MT; mt++) {
        int r0 = rowBase + wm * WM + mt * 16 + (lane >> 2);
        #pragma unroll
        for (int nt = 0; nt < NT; nt++) {
            int c = colBase + wn * WN + nt * 8 + (lane & 3) * 2;
            #pragma unroll
            for (int hh = 0; hh < 2; hh++) {
                int r = r0 + hh * 8;
                float v0 = acc[mt][nt][hh * 2 + 0] * oscale;
                float v1 = acc[mt][nt][hh * 2 + 1] * oscale;
                if (BIAS) { v0 += bias[c]; v1 += bias[c + 1]; }
                if (GELU) { v0 = gelu_f(v0); v1 = gelu_f(v1); }
                if (RES)  {
                    float2 rr = *(const float2*)(R + (size_t)r * ldr + c);
                    v0 += rr.x; v1 += rr.y;
                }
                if (OUTH) *(__half2*)(Ch + (size_t)r * ldc + c) = __floats2half2_rn(v0, v1);
                else      *(float2*) (Cf + (size_t)r * ldc + c) = make_float2(v0, v1);
            }
        }
    }
}

// ---------------- fused flash attention ----------------------------------------
// grid (SEQ/128, HEADS, BATCH), 256 threads. Q pre-scaled by 1/sqrt(dk).
// ctx written as half in [tok][DM] layout (col offset h*64).
struct FlashSmem {
    __half Qs[128][72];
    __half Ks[2][64][72];
    __half Vs[2][64][72];
    unsigned char Ms[2][128][64];
};

__global__ void __launch_bounds__(256)
flash_kernel(const __half* __restrict__ q, const __half* __restrict__ k,
             const __half* __restrict__ v, const unsigned char* __restrict__ mask,
             __half* __restrict__ ctx)
{
    const int BN = 64;
    extern __shared__ char smem_raw[];
    FlashSmem& S = *reinterpret_cast<FlashSmem*>(smem_raw);

    int qb = blockIdx.x * 128;
    int h  = blockIdx.y, b = blockIdx.z;
    int tid = threadIdx.x, warp = tid >> 5, lane = tid & 31;

    const __half* qp = q + ((size_t)(b * SEQ + qb)) * DM + h * DH;
    const __half* kp = k + ((size_t)b * SEQ) * DM + h * DH;
    const __half* vp = v + ((size_t)b * SEQ) * DM + h * DH;
    const unsigned char* mp = mask + ((size_t)(b * SEQ + qb)) * SEQ;

    // stage Q (128 rows x 64 halves)
    #pragma unroll
    for (int j = 0; j < 4; j++) {
        int idx = j * 256 + tid;
        int r = idx >> 3, c = idx & 7;
        CP_ASYNC16(smem_u32(&S.Qs[r][c * 8]), qp + (size_t)r * DM + c * 8);
    }

    auto stageKV = [&](int buf, int kb) {
        #pragma unroll
        for (int j = 0; j < 2; j++) {
            int idx = j * 256 + tid;
            int r = idx >> 3, c = idx & 7;
            CP_ASYNC16(smem_u32(&S.Ks[buf][r][c * 8]), kp + (size_t)(kb + r) * DM + c * 8);
        }
        #pragma unroll
        for (int j = 0; j < 2; j++) {
            int idx = j * 256 + tid;
            int r = idx >> 3, c = idx & 7;
            CP_ASYNC16(smem_u32(&S.Vs[buf][r][c * 8]), vp + (size_t)(kb + r) * DM + c * 8);
        }
        #pragma unroll
        for (int j = 0; j < 2; j++) {
            int idx = j * 256 + tid;
            int r = idx >> 2, c = idx & 3;
            CP_ASYNC16(smem_u32(&S.Ms[buf][r][c * 16]), mp + (size_t)r * SEQ + kb + c * 16);
        }
    };

    stageKV(0, 0);
    CP_COMMIT();
    CP_WAIT(0);
    __syncthreads();

    // Q fragments (16 rows x 64 d per warp)
    uint32_t qf[4][4];
    #pragma unroll
    for (int ks = 0; ks < 4; ks++) {
        uint32_t ad = smem_u32(&S.Qs[warp * 16 + (lane & 15)][ks * 16 + (lane >> 4) * 8]);
        LDSM4(qf[ks][0], qf[ks][1], qf[ks][2], qf[ks][3], ad);
    }

    float oacc[8][4];
    #pragma unroll
    for (int dt = 0; dt < 8; dt++)
        #pragma unroll
        for (int i = 0; i < 4; i++) oacc[dt][i] = 0.f;
    float m0 = -1e30f, m1 = -1e30f, l0 = 0.f, l1 = 0.f;
    int rloc = warp * 16 + (lane >> 2);

    const int NIT = SEQ / BN;
    for (int it = 0; it < NIT; it++) {
        int buf = it & 1;
        if (it + 1 < NIT) { stageKV(buf ^ 1, (it + 1) * BN); CP_COMMIT(); }

        // ---- S = Q @ K^T  (16 x 64 per warp) ----
        float s[8][4];
        #pragma unroll
        for (int nt = 0; nt < 8; nt++)
            #pragma unroll
            for (int i = 0; i < 4; i++) s[nt][i] = 0.f;

        #pragma unroll
        for (int g = 0; g < 4; g++) {              // key group of 16
            #pragma unroll
            for (int ks = 0; ks < 4; ks++) {       // d chunk of 16
                uint32_t kf0, kf1, kf2, kf3;
                LDSM4(kf0, kf1, kf2, kf3,
                      smem_u32(&S.Ks[buf][g * 16 + (lane & 15)][ks * 16 + (lane >> 4) * 8]));
                MMA16816(s[2*g][0], s[2*g][1], s[2*g][2], s[2*g][3],
                         qf[ks][0], qf[ks][1], qf[ks][2], qf[ks][3], kf0, kf2);
                MMA16816(s[2*g+1][0], s[2*g+1][1], s[2*g+1][2], s[2*g+1][3],
                         qf[ks][0], qf[ks][1], qf[ks][2], qf[ks][3], kf1, kf3);
            }
        }

        // ---- mask ----
        #pragma unroll
        for (int nt = 0; nt < 8; nt++) {
            int c = nt * 8 + (lane & 3) * 2;
            uchar2 ma = *(const uchar2*)&S.Ms[buf][rloc][c];
            uchar2 mb = *(const uchar2*)&S.Ms[buf][rloc + 8][c];
            if (ma.x) s[nt][0] = -1e9f;
            if (ma.y) s[nt][1] = -1e9f;
            if (mb.x) s[nt][2] = -1e9f;
            if (mb.y) s[nt][3] = -1e9f;
        }

        // ---- online softmax ----
        float cm0 = -1e30f, cm1 = -1e30f;
        #pragma unroll
        for (int nt = 0; nt < 8; nt++) {
            cm0 = fmaxf(cm0, fmaxf(s[nt][0], s[nt][1]));
            cm1 = fmaxf(cm1, fmaxf(s[nt][2], s[nt][3]));
        }
        cm0 = fmaxf(cm0, __shfl_xor_sync(0xffffffffu, cm0, 1));
        cm0 = fmaxf(cm0, __shfl_xor_sync(0xffffffffu, cm0, 2));
        cm1 = fmaxf(cm1, __shfl_xor_sync(0xffffffffu, cm1, 1));
        cm1 = fmaxf(cm1, __shfl_xor_sync(0xffffffffu, cm1, 2));

        float mn0 = fmaxf(m0, cm0), mn1 = fmaxf(m1, cm1);
        float sc0 = __expf(m0 - mn0), sc1 = __expf(m1 - mn1);
        m0 = mn0; m1 = mn1;

        uint32_t pf[8][2];
        float rs0 = 0.f, rs1 = 0.f;
        #pragma unroll
        for (int nt = 0; nt < 8; nt++) {
            float p0 = __expf(s[nt][0] - m0);
            float p1 = __expf(s[nt][1] - m0);
            float p2 = __expf(s[nt][2] - m1);
            float p3 = __expf(s[nt][3] - m1);
            rs0 += p0 + p1; rs1 += p2 + p3;
            pf[nt][0] = h2u(p0, p1);
            pf[nt][1] = h2u(p2, p3);
        }
        l0 = l0 * sc0 + rs0;
        l1 = l1 * sc1 + rs1;
        #pragma unroll
        for (int dt = 0; dt < 8; dt++) {
            oacc[dt][0] *= sc0; oacc[dt][1] *= sc0;
            oacc[dt][2] *= sc1; oacc[dt][3] *= sc1;
        }

        // ---- O += P @ V  (full d = 64: g covers 4 x 16) ----
        #pragma unroll
        for (int kk = 0; kk < 4; kk++) {           // key chunk of 16
            #pragma unroll
            for (int g = 0; g < 4; g++) {          // d group of 16 (2 tiles each)
                uint32_t vf0, vf1, vf2, vf3;
                LDSM4T(vf0, vf1, vf2, vf3,
                       smem_u32(&S.Vs[buf][kk * 16 + (lane & 15)][g * 16 + (lane >> 4) * 8]));
                MMA16816(oacc[2*g][0], oacc[2*g][1], oacc[2*g][2], oacc[2*g][3],
                         pf[2*kk][0], pf[2*kk][1], pf[2*kk+1][0], pf[2*kk+1][1], vf0, vf1);
                MMA16816(oacc[2*g+1][0], oacc[2*g+1][1], oacc[2*g+1][2], oacc[2*g+1][3],
                         pf[2*kk][0], pf[2*kk][1], pf[2*kk+1][0], pf[2*kk+1][1], vf2, vf3);
            }
        }

        if (it + 1 < NIT) { CP_WAIT(0); }
        __syncthreads();
    }

    // final normalization: reduce partial sums across quad
    l0 += __shfl_xor_sync(0xffffffffu, l0, 1);
    l0 += __shfl_xor_sync(0xffffffffu, l0, 2);
    l1 += __shfl_xor_sync(0xffffffffu, l1, 1);
    l1 += __shfl_xor_sync(0xffffffffu, l1, 2);
    float inv0 = 1.0f / l0, inv1 = 1.0f / l1;

    size_t row0 = (size_t)(b * SEQ + qb + rloc);
    #pragma unroll
    for (int dt = 0; dt < 8; dt++) {
        int col = h * DH + dt * 8 + (lane & 3) * 2;
        *(__half2*)(ctx + row0 * DM + col)       = __floats2half2_rn(oacc[dt][0] * inv0, oacc[dt][1] * inv0);
        *(__half2*)(ctx + (row0 + 8) * DM + col) = __floats2half2_rn(oacc[dt][2] * inv1, oacc[dt][3] * inv1);
    }
}

// ---------------- fp32 -> half convert ----------------------------------------
__global__ __launch_bounds__(256)
void cvt_kernel(const float* __restrict__ s, __half* __restrict__ d, int n)
{
    int i = (blockIdx.x * 256 + threadIdx.x) * 4;
    if (i < n) {
        float4 v = *(const float4*)(s + i);
        *(__half2*)(d + i)     = __floats2half2_rn(v.x, v.y);
        *(__half2*)(d + i + 2) = __floats2half2_rn(v.z, v.w);
    }
}

// ---------------- LayerNorm -> half --------------------------------------------
__global__ __launch_bounds__(256)
void ln_half_kernel(const float* __restrict__ x, const float* __restrict__ g,
                    const float* __restrict__ b, __half* __restrict__ out)
{
    int row = blockIdx.x;
    int tid = threadIdx.x;
    float4 v = reinterpret_cast<const float4*>(x + (size_t)row * DM)[tid];
    float s  = v.x + v.y + v.z + v.w;
    float s2 = v.x * v.x + v.y * v.y + v.z * v.z + v.w * v.w;

    __shared__ float red[64];
    for (int o = 16; o; o >>= 1) {
        s  += __shfl_xor_sync(0xffffffffu, s,  o);
        s2 += __shfl_xor_sync(0xffffffffu, s2, o);
    }
    int warp = tid >> 5, lane = tid & 31;
    if (lane == 0) { red[warp] = s; red[32 + warp] = s2; }
    __syncthreads();
    if (warp == 0) {
        float a = (lane < 8) ? red[lane] : 0.f;
        float c = (lane < 8) ? red[32 + lane] : 0.f;
        for (int o = 4; o; o >>= 1) {
            a += __shfl_xor_sync(0xffffffffu, a, o);
            c += __shfl_xor_sync(0xffffffffu, c, o);
        }
        if (lane == 0) { red[0] = a; red[1] = c; }
    }
    __syncthreads();
    float mu   = red[0] * (1.0f / DM);
    float var  = red[1] * (1.0f / DM) - mu * mu;
    float rstd = rsqrtf(var + 1e-5f);

    float4 gv = reinterpret_cast<const float4*>(g)[tid];
    float4 bv = reinterpret_cast<const float4*>(b)[tid];
    float o0 = (v.x - mu) * rstd * gv.x + bv.x;
    float o1 = (v.y - mu) * rstd * gv.y + bv.y;
    float o2 = (v.z - mu) * rstd * gv.z + bv.z;
    float o3 = (v.w - mu) * rstd * gv.w + bv.w;
    __half2* op = reinterpret_cast<__half2*>(out + (size_t)row * DM);
    op[tid * 2]     = __floats2half2_rn(o0, o1);
    op[tid * 2 + 1] = __floats2half2_rn(o2, o3);
}

// ---------------- launch --------------------------------------------------------
extern "C" void kernel_launch(void* const* d_in, const int* in_sizes, int n_in,
                              void* d_out, int out_size)
{
    const float* x     = (const float*)d_in[0];
    const unsigned char* pad = (const unsigned char*)d_in[1];
    const float* W_Q   = (const float*)d_in[2];
    const float* W_K   = (const float*)d_in[3];
    const float* W_V   = (const float*)d_in[4];
    const float* W_O   = (const float*)d_in[5];
    const float* fc1_w = (const float*)d_in[6];
    const float* fc1_b = (const float*)d_in[7];
    const float* fc2_w = (const float*)d_in[8];
    const float* fc2_b = (const float*)d_in[9];
    const float* ln1_g = (const float*)d_in[10];
    const float* ln1_b = (const float*)d_in[11];
    const float* ln2_g = (const float*)d_in[12];
    const float* ln2_b = (const float*)d_in[13];
    float* out = (float*)d_out;

    __half *hh, *qh, *kh, *vh, *ctxh, *ff, *wq, *wk, *wv, *wo, *w1, *w2;
    float *x2;
    cudaGetSymbolAddress((void**)&hh,   g_hh);
    cudaGetSymbolAddress((void**)&qh,   g_qh);
    cudaGetSymbolAddress((void**)&kh,   g_kh);
    cudaGetSymbolAddress((void**)&vh,   g_vh);
    cudaGetSymbolAddress((void**)&ctxh, g_ctx);
    cudaGetSymbolAddress((void**)&x2,   g_x2);
    cudaGetSymbolAddress((void**)&ff,   g_ff);
    cudaGetSymbolAddress((void**)&wq,   g_wq);
    cudaGetSymbolAddress((void**)&wk,   g_wk);
    cudaGetSymbolAddress((void**)&wv,   g_wv);
    cudaGetSymbolAddress((void**)&wo,   g_wo);
    cudaGetSymbolAddress((void**)&w1,   g_w1);
    cudaGetSymbolAddress((void**)&w2,   g_w2);

    // 0) weights -> half
    cvt_kernel<<<DM*DM/1024, 256>>>(W_Q, wq, DM*DM);
    cvt_kernel<<<DM*DM/1024, 256>>>(W_K, wk, DM*DM);
    cvt_kernel<<<DM*DM/1024, 256>>>(W_V, wv, DM*DM);
    cvt_kernel<<<DM*DM/1024, 256>>>(W_O, wo, DM*DM);
    cvt_kernel<<<DM*DFF/1024, 256>>>(fc1_w, w1, DM*DFF);
    cvt_kernel<<<DFF*DM/1024, 256>>>(fc2_w, w2, DFF*DM);

    // 1) LN1 -> half
    ln_half_kernel<<<TOK, 256>>>(x, ln1_g, ln1_b, hh);

    // 2) QKV projections (q pre-scaled by 1/sqrt(dk))
    dim3 gP(DM/128, TOK/128);
    hgemm<128,128,64,32,false,false,false,true><<<gP,256>>>(
        hh, DM, wq, DM, nullptr, nullptr,0, qh, DM, TOK, DM, DM, 0.125f);
    hgemm<128,128,64,32,false,false,false,true><<<gP,256>>>(
        hh, DM, wk, DM, nullptr, nullptr,0, kh, DM, TOK, DM, DM, 1.0f);
    hgemm<128,128,64,32,false,false,false,true><<<gP,256>>>(
        hh, DM, wv, DM, nullptr, nullptr,0, vh, DM, TOK, DM, DM, 1.0f);

    // 3) fused attention -> ctx (half, [tok][DM])
    static int smem_set = 0;
    if (!smem_set) {
        cudaFuncSetAttribute(flash_kernel, cudaFuncAttributeMaxDynamicSharedMemorySize,
                             (int)sizeof(FlashSmem));
        smem_set = 1;
    }
    dim3 gA(SEQ/128, HEADS, BATCH);
    flash_kernel<<<gA, 256, sizeof(FlashSmem)>>>(qh, kh, vh, pad, ctxh);

    // 4) O-proj + residual(x) -> x2 fp32
    hgemm<128,128,64,32,false,false,true,false><<<gP,256>>>(
        ctxh, DM, wo, DM, nullptr, x, DM, x2, DM, TOK, DM, DM, 1.0f);

    // 5) LN2 -> half
    ln_half_kernel<<<TOK, 256>>>(x2, ln2_g, ln2_b, hh);

    // 6) FC1 + bias + gelu -> half
    dim3 gF(DFF/128, TOK/128);
    hgemm<128,128,64,32,true,true,false,true><<<gF,256>>>(
        hh, DM, w1, DFF, fc1_b, nullptr,0, ff, DFF, TOK, DFF, DM, 1.0f);

    // 7) FC2 + bias + residual(x2) -> out fp32
    hgemm<128,128,64,32,true,false,true,false><<<gP,256>>>(
        ff, DFF, w2, DM, fc2_b, x2, DM, out, DM, TOK, DM, DFF, 1.0f);
}